// round 5
// baseline (speedup 1.0000x reference)
#include <cuda_runtime.h>
#include <math.h>

#define N_NODES   8192
#define HIDDEN    256
#define HEADS     4
#define HEAD_DIM  64
#define NUM_EDGES 4096
#define NUM_INC   65536
#define OUT_ELEMS (N_NODES*HIDDEN)
#define MT 64
#define KT 16
#define NB_MEGA 256

// ---------------- scratch (device globals) ----------------
__device__ float    g_v[HEADS*HIDDEN];
__device__ float    g_bh[HEADS];
__device__ float    g_nlogit[N_NODES*HEADS];   // float4 per node
__device__ int      g_ecount[NUM_EDGES];
__device__ int      g_estart[NUM_EDGES+1];
__device__ int      g_efill[NUM_EDGES];
__device__ int      g_ncount[N_NODES];
__device__ int      g_nstart[N_NODES+1];
__device__ int      g_nfill[N_NODES];
__device__ int      g_ecols[NUM_INC];   // edge-CSR: member node ids
__device__ int      g_enpos[NUM_INC];   // edge-CSR: node-CSR position of that incidence
__device__ int      g_nedge[NUM_INC];   // node-CSR: edge id of incidence
__device__ float    g_attn_np[NUM_INC]; // attn per incidence, node-CSR order
__device__ float    g_nattn[N_NODES];

// ---------------- grid-wide spin barrier (generation-monotonic) ----------------
__device__ int      g_cnt = 0;
__device__ unsigned g_gen = 0;

__device__ __forceinline__ void gbar(){
    __syncthreads();
    if (threadIdx.x == 0){
        unsigned g = *(volatile unsigned*)&g_gen;
        __threadfence();
        if (atomicAdd(&g_cnt, 1) == NB_MEGA-1){
            g_cnt = 0;
            __threadfence();
            atomicAdd(&g_gen, 1);
        } else {
            while (*(volatile unsigned*)&g_gen == g) {}
        }
    }
    __syncthreads();
}

// ---------------- 256-thread prefix scan (recompute, no big local arrays) ---------
__device__ void scan256(const int* __restrict__ cnt, int* __restrict__ start,
                        int IPT, int NITEMS){
    __shared__ int sh[256];
    int t = threadIdx.x;
    int base = t*IPT;
    int run = 0;
    for (int k = 0; k < IPT; k++) run += cnt[base+k];
    sh[t] = run;
    __syncthreads();
    for (int off = 1; off < 256; off <<= 1){
        int v = (t >= off) ? sh[t-off] : 0;
        __syncthreads();
        sh[t] += v;
        __syncthreads();
    }
    int prev = t ? sh[t-1] : 0;
    for (int k = 0; k < IPT; k++){ start[base+k] = prev; prev += cnt[base+k]; }
    if (t == 255) start[NITEMS] = sh[255];
}

// ================= MEGA: init+prep | count+nlogit | scans | fill | softmax =========
__global__ __launch_bounds__(256, 4) void k_mega(const float* __restrict__ x,
                                                 const int* __restrict__ node_idx,
                                                 const int* __restrict__ edge_idx,
                                                 const float* __restrict__ W_w,
                                                 const float* __restrict__ W_b,
                                                 const float* __restrict__ att){
    __shared__ float sv[HEADS*HIDDEN];
    int tid = threadIdx.x;
    int bid = blockIdx.x;
    int gtid = bid*256 + tid;

    // ---- P0: zero counters + prep g_v ----
    if (bid < 32){
        int i = bid*256 + tid;
        g_ncount[i] = 0; g_nfill[i] = 0; g_nattn[i] = 0.f;
        if (i < NUM_EDGES){ g_ecount[i] = 0; g_efill[i] = 0; }
    } else if (bid == 255){
        int k = tid;
        #pragma unroll
        for (int h = 0; h < HEADS; h++){
            float s = 0.f;
            #pragma unroll 8
            for (int d = 0; d < HEAD_DIM; d++)
                s += W_w[(h*HEAD_DIM + d)*HIDDEN + k] * att[h*HEAD_DIM + d];
            g_v[h*HIDDEN + k] = s;
        }
        if (k < HEADS){
            float s = 0.f;
            #pragma unroll 8
            for (int d = 0; d < HEAD_DIM; d++)
                s += W_b[k*HEAD_DIM + d] * att[k*HEAD_DIM + d];
            g_bh[k] = s;
        }
    }
    gbar();

    // ---- P1: count (1 incidence/thread) + nlogit (8 threads/node) ----
    {
        // start sv load (needs g_v from P0)
        #pragma unroll
        for (int i = 0; i < 4; i++) sv[tid + 256*i] = g_v[tid + 256*i];

        int e = edge_idx[gtid], nn = node_idx[gtid];
        atomicAdd(&g_ecount[e], 1);
        atomicAdd(&g_ncount[nn], 1);
        __syncthreads();

        int c = gtid & 7;
        int n = gtid >> 3;
        const float4* xr = (const float4*)(x + (long)n*HIDDEN);
        const float4* v0 = (const float4*)(sv);
        const float4* v1 = (const float4*)(sv + 256);
        const float4* v2 = (const float4*)(sv + 512);
        const float4* v3 = (const float4*)(sv + 768);
        float a0=0.f, a1=0.f, a2=0.f, a3=0.f;
        #pragma unroll
        for (int i = 0; i < 8; i++){
            int j = i*8 + c;
            float4 xv = xr[j];
            float4 w;
            w = v0[j]; a0 += xv.x*w.x + xv.y*w.y + xv.z*w.z + xv.w*w.w;
            w = v1[j]; a1 += xv.x*w.x + xv.y*w.y + xv.z*w.z + xv.w*w.w;
            w = v2[j]; a2 += xv.x*w.x + xv.y*w.y + xv.z*w.z + xv.w*w.w;
            w = v3[j]; a3 += xv.x*w.x + xv.y*w.y + xv.z*w.z + xv.w*w.w;
        }
        #pragma unroll
        for (int off = 1; off < 8; off <<= 1){
            a0 += __shfl_xor_sync(0xffffffffu, a0, off);
            a1 += __shfl_xor_sync(0xffffffffu, a1, off);
            a2 += __shfl_xor_sync(0xffffffffu, a2, off);
            a3 += __shfl_xor_sync(0xffffffffu, a3, off);
        }
        if (c == 0){
            float4 r = make_float4(a0 + g_bh[0], a1 + g_bh[1], a2 + g_bh[2], a3 + g_bh[3]);
            ((float4*)g_nlogit)[n] = r;
        }
    }
    gbar();

    // ---- P2: prefix scans ----
    if (bid == 0)      scan256(g_ecount, g_estart, NUM_EDGES/256, NUM_EDGES);
    else if (bid == 1) scan256(g_ncount, g_nstart, N_NODES/256,  N_NODES);
    gbar();

    // ---- P3: fill both CSRs ----
    {
        int e = edge_idx[gtid], n = node_idx[gtid];
        int pe = atomicAdd(&g_efill[e], 1);
        int pn = atomicAdd(&g_nfill[n], 1);
        int epos = g_estart[e] + pe;
        int npos = g_nstart[n] + pn;
        g_ecols[epos] = n;
        g_enpos[epos] = npos;
        g_nedge[npos] = e;
    }
    gbar();

    // ---- P4: per-edge softmax (warp per edge, 2 edges/warp) ----
    {
        int lane = tid & 31;
        int wbase = (bid*8 + (tid >> 5)) * 2;
        const float4* NL = (const float4*)g_nlogit;
        #pragma unroll
        for (int ew = 0; ew < 2; ew++){
            int gw = wbase + ew;
            int s = g_estart[gw], cnt = g_ecount[gw];
            if (cnt == 0) continue;

            float m0=-1e30f, m1=-1e30f, m2=-1e30f, m3=-1e30f;
            for (int t = lane; t < cnt; t += 32){
                float4 l = NL[g_ecols[s+t]];
                m0 = fmaxf(m0, l.x); m1 = fmaxf(m1, l.y);
                m2 = fmaxf(m2, l.z); m3 = fmaxf(m3, l.w);
            }
            #pragma unroll
            for (int off = 16; off; off >>= 1){
                m0 = fmaxf(m0, __shfl_xor_sync(0xffffffffu, m0, off));
                m1 = fmaxf(m1, __shfl_xor_sync(0xffffffffu, m1, off));
                m2 = fmaxf(m2, __shfl_xor_sync(0xffffffffu, m2, off));
                m3 = fmaxf(m3, __shfl_xor_sync(0xffffffffu, m3, off));
            }
            float s0=0.f, s1=0.f, s2=0.f, s3=0.f;
            for (int t = lane; t < cnt; t += 32){
                float4 l = NL[g_ecols[s+t]];
                s0 += expf(l.x - m0); s1 += expf(l.y - m1);
                s2 += expf(l.z - m2); s3 += expf(l.w - m3);
            }
            #pragma unroll
            for (int off = 16; off; off >>= 1){
                s0 += __shfl_xor_sync(0xffffffffu, s0, off);
                s1 += __shfl_xor_sync(0xffffffffu, s1, off);
                s2 += __shfl_xor_sync(0xffffffffu, s2, off);
                s3 += __shfl_xor_sync(0xffffffffu, s3, off);
            }
            bool valid = (cnt >= 2);
            float r0 = 1.f/s0, r1 = 1.f/s1, r2 = 1.f/s2, r3 = 1.f/s3;
            for (int t = lane; t < cnt; t += 32){
                int col = g_ecols[s+t];
                float a = 0.f;
                if (valid){
                    float4 l = NL[col];
                    a = 0.25f*(expf(l.x - m0)*r0 + expf(l.y - m1)*r1 +
                               expf(l.z - m2)*r2 + expf(l.w - m3)*r3);
                }
                g_attn_np[g_enpos[s+t]] = a;
                atomicAdd(&g_nattn[col], a);
            }
        }
    }
}

// ================= K6: AW row writer (b<8192) || fused GEMM+LN (last 128) ==========
__global__ __launch_bounds__(256) void k6(const float* __restrict__ x,
                                          const float* __restrict__ out_w,
                                          const float* __restrict__ out_b,
                                          float* __restrict__ out,
                                          float* __restrict__ AW){
    extern __shared__ float smf[];
    int tid = threadIdx.x;

    if (blockIdx.x >= N_NODES){
        float (*As)[MT+1]     = (float(*)[MT+1])smf;                    // 16 x 65
        float (*Bs)[HIDDEN+1] = (float(*)[HIDDEN+1])(smf + KT*(MT+1));  // 16 x 257
        float* Ss             = smf + KT*(MT+1) + KT*(HIDDEN+1);        // 64
        int tx = tid & 15;
        int ty = tid >> 4;
        int row0 = (blockIdx.x - N_NODES) * MT;

        if (tid < MT){
            int rr = row0 + tid;
            float c = (float)g_ncount[rr];
            Ss[tid] = g_nattn[rr] / fmaxf(c, 1.0f);
        }
        __syncthreads();

        float acc[4][16];
        #pragma unroll
        for (int i = 0; i < 4; i++)
            #pragma unroll
            for (int j = 0; j < 16; j++) acc[i][j] = 0.f;

        for (int k0 = 0; k0 < HIDDEN; k0 += KT){
            #pragma unroll
            for (int r = 0; r < 4; r++){                 // A: 64x16
                int q = tid + 256*r;
                int m = q >> 4, k = q & 15;
                As[k][m] = x[(long)(row0+m)*HIDDEN + k0 + k] * Ss[m];
            }
            #pragma unroll
            for (int r = 0; r < 16; r++){                // B: 256x16
                int q = tid + 256*r;
                int j = q >> 4, k = q & 15;
                Bs[k][j] = out_w[(long)j*HIDDEN + k0 + k];
            }
            __syncthreads();
            #pragma unroll
            for (int k = 0; k < KT; k++){
                float a[4], b[16];
                #pragma unroll
                for (int i = 0; i < 4; i++) a[i] = As[k][ty*4 + i];
                #pragma unroll
                for (int j = 0; j < 16; j++) b[j] = Bs[k][tx + 16*j];
                #pragma unroll
                for (int i = 0; i < 4; i++)
                    #pragma unroll
                    for (int j = 0; j < 16; j++) acc[i][j] += a[i]*b[j];
            }
            __syncthreads();
        }

        #pragma unroll
        for (int j = 0; j < 16; j++){
            float bb = out_b[tx + 16*j];
            #pragma unroll
            for (int i = 0; i < 4; i++) acc[i][j] += bb;
        }

        #pragma unroll
        for (int i = 0; i < 4; i++){
            float s = 0.f, s2 = 0.f;
            #pragma unroll
            for (int j = 0; j < 16; j++){ s += acc[i][j]; s2 += acc[i][j]*acc[i][j]; }
            #pragma unroll
            for (int off = 8; off; off >>= 1){
                s  += __shfl_xor_sync(0xffffffffu, s,  off);
                s2 += __shfl_xor_sync(0xffffffffu, s2, off);
            }
            float mu  = s * (1.f/256.f);
            float var = s2 * (1.f/256.f) - mu*mu;
            float inv = rsqrtf(var + 1e-5f);
            int row = row0 + ty*4 + i;
            float* op = out + (long)row*HIDDEN;
            #pragma unroll
            for (int j = 0; j < 16; j++)
                op[tx + 16*j] = (acc[i][j] - mu) * inv;
        }
    } else {
        // ---- one dense AW row per block ----
        __shared__ float sa[64];
        __shared__ int   ses[64];
        __shared__ int   sec[64];
        __shared__ int   sarr[64];
        float* srow = smf;                   // 8192 floats
        float4* srow4 = (float4*)srow;
        float4 z4 = make_float4(0.f,0.f,0.f,0.f);
        #pragma unroll
        for (int i = 0; i < 8; i++) srow4[tid + 256*i] = z4;
        __syncthreads();

        int n = blockIdx.x;
        int s = g_nstart[n], dcnt = g_ncount[n];

        for (int base = 0; base < dcnt; base += 64){
            int m = min(64, dcnt - base);
            if (tid < m){
                float a = g_attn_np[s + base + tid];
                int e   = g_nedge[s + base + tid];
                int es  = g_estart[e];
                int ec  = (a != 0.f) ? g_ecount[e] : 0;
                sa[tid]  = a;
                ses[tid] = es;
                sec[tid] = ec;
                sarr[tid] = ec;
            }
            __syncthreads();
            for (int off = 1; off < 64; off <<= 1){
                int v = 0;
                if (tid < m && tid >= off) v = sarr[tid - off];
                __syncthreads();
                if (tid < m && tid >= off) sarr[tid] += v;
                __syncthreads();
            }
            int T = sarr[m-1];
            for (int t = tid; t < T; t += 256){
                int lo = 0, hi = m-1;
                while (lo < hi){
                    int mid = (lo + hi) >> 1;
                    if (sarr[mid] > t) hi = mid; else lo = mid + 1;
                }
                int off = t - (sarr[lo] - sec[lo]);
                int col = g_ecols[ses[lo] + off];
                atomicAdd(&srow[col], sa[lo]);
            }
            __syncthreads();
        }
        if (tid == 0) srow[n] = 0.f;         // diagonal
        __syncthreads();
        float4* dst = (float4*)(AW + (long)n*N_NODES);
        #pragma unroll
        for (int i = 0; i < 8; i++)
            __stcs(dst + tid + 256*i, srow4[tid + 256*i]);
    }
}

// ---------------- launch ----------------
extern "C" void kernel_launch(void* const* d_in, const int* in_sizes, int n_in,
                              void* d_out, int out_size){
    const float* x        = (const float*)d_in[0];
    const int*   node_idx = (const int*)  d_in[1];
    const int*   edge_idx = (const int*)  d_in[2];
    const float* W_w      = (const float*)d_in[3];
    const float* W_b      = (const float*)d_in[4];
    const float* att      = (const float*)d_in[5];
    const float* out_w    = (const float*)d_in[6];
    const float* out_b    = (const float*)d_in[7];
    float* out = (float*)d_out;
    float* AW  = out + OUT_ELEMS;

    const int smem6 = 8192 * sizeof(float); // 32768 (>= GEMM's 20864)
    k_mega<<<NB_MEGA, 256>>>(x, node_idx, edge_idx, W_w, W_b, att);
    k6<<<N_NODES + N_NODES/MT, 256, smem6>>>(x, out_w, out_b, out, AW);
}